// round 3
// baseline (speedup 1.0000x reference)
#include <cuda_runtime.h>

// DynamicRelationshipExtractor — GB300 sm_103a, round 3
//   - 192 threads/CTA, TP=48 pairs, 2 CTAs/SM (smem 109KB, regs<=168)
//   - hid-update GEMM retiled: warp = 16p x 128q, thread = 4p x 16q
//     (weight LDS dedup 4x across p-groups; acts float4 over c)
//   - tokb aliased over feats; hid aliased over xs+feats

#define EPSF 1e-6f
#define NT 192

static const int NC = 64;
static const int Dd = 128;
static const int Pp = 2016;
static const int TP = 48;

typedef unsigned long long u64;

__device__ __forceinline__ u64 pk2(float x, float y) {
    u64 r; asm("mov.b64 %0, {%1, %2};" : "=l"(r) : "f"(x), "f"(y)); return r;
}
__device__ __forceinline__ u64 dup2(float x) {
    u64 r; asm("mov.b64 %0, {%1, %1};" : "=l"(r) : "f"(x)); return r;
}
__device__ __forceinline__ void fma2(u64 &d, u64 a, u64 b) {
    asm("fma.rn.f32x2 %0, %1, %2, %0;" : "+l"(d) : "l"(a), "l"(b));
}
__device__ __forceinline__ void up2(u64 v, float &x, float &y) {
    asm("mov.b64 {%0, %1}, %2;" : "=f"(x), "=f"(y) : "l"(v));
}

// shared layout (floats)
#define OFF_XS     0                         // 8192
#define OFF_FEATS  8192                      // 48*132 = 6336 (tokb aliases here)
#define OFF_HB     (OFF_FEATS + 48*132)      // 14528, 48*68 = 3264
#define OFF_WB     (OFF_HB + 48*68)          // 17792, 8192
#define OFF_PCON   (OFF_WB + 8192)           // 25984, 1024
#define OFF_PTOK4  (OFF_PCON + 1024)         // 512
#define OFF_PH4    (OFF_PTOK4 + 512)         // 256
#define OFF_INORM  (OFF_PH4 + 256)           // 64
#define OFF_INTS   (OFF_INORM + 64)          // 3*48 ints
#define SMEM_FLOATS (OFF_INTS + 3*48)
#define SMEM_BYTES  (SMEM_FLOATS*4)
#define OFF_HID    0                          // alias over xs+feats: 48*260=12480 <= 14528

__device__ __forceinline__ float featf(int k, float a, float c, float ni, float nj) {
    switch (k) {
        case 0: return a * c;
        case 1: return a + c;
        case 2: return (a * ni) * (c * nj);
        case 3: return fabsf(a - c);
        case 4: return a - c;
        case 5: return c - a;
        case 6: return __fdiv_rn(a, c + EPSF);
        default: return __fdiv_rn(c, a + EPSF);
    }
}

__device__ __forceinline__ void stage8192(const float* __restrict__ g, float* s, int tid) {
    const float4* src = (const float4*)g;
    float4* dst = (float4*)s;
    #pragma unroll 1
    for (int i = tid; i < 2048; i += NT) dst[i] = src[i];
}

__global__ void __launch_bounds__(NT, 2)
dre_kernel(const float* __restrict__ x, const int* __restrict__ presence,
           const int* __restrict__ idx_i, const int* __restrict__ idx_j,
           const float* __restrict__ oW1, const float* __restrict__ ob1,
           const float* __restrict__ oW2, const float* __restrict__ ob2,
           const float* __restrict__ pW1, const float* __restrict__ pb1,
           const float* __restrict__ pW2, const float* __restrict__ pb2,
           const float* __restrict__ fW1, const float* __restrict__ fb1,
           const float* __restrict__ fW2, const float* __restrict__ fb2,
           float* __restrict__ out)
{
    extern __shared__ float sm[];
    float* xs    = sm + OFF_XS;
    float* feats = sm + OFF_FEATS;
    float* tokb  = sm + OFF_FEATS;   // alias
    float* hb    = sm + OFF_HB;
    float* wb    = sm + OFF_WB;
    float* pcon  = sm + OFF_PCON;
    float* ptok4 = sm + OFF_PTOK4;
    float* ph4   = sm + OFF_PH4;
    float* inorm = sm + OFF_INORM;
    int*   pi    = (int*)(sm + OFF_INTS);
    int*   pj    = pi + 48;
    int*   pcx   = pj + 48;

    const int tid = threadIdx.x;
    const int b   = blockIdx.y;
    const int p0  = blockIdx.x * TP;

    // ---- load x[b] into shared ----
    {
        const float4* src = (const float4*)(x + (size_t)b * NC * Dd);
        float4* dst = (float4*)xs;
        #pragma unroll 1
        for (int i = tid; i < 2048; i += NT) dst[i] = src[i];
    }
    // ---- pair indices + presence class ----
    if (tid < TP) {
        int pp = p0 + tid;
        int ii = idx_i[pp], jj = idx_j[pp];
        pi[tid] = ii; pj[tid] = jj;
        int pa = presence[b*NC + ii], pb_ = presence[b*NC + jj];
        pcx[tid] = pa ? (pb_ ? 0 : 1) : (pb_ ? 2 : 3);
    }
    // ---- ph4 = relu(pres_W1[c] + pres_b1) ----
    #pragma unroll 1
    for (int o = tid; o < 256; o += NT) {
        int c = o >> 6, t = o & 63;
        float v = pW1[c*64 + t] + pb1[t];
        ph4[o] = v > 0.f ? v : 0.f;
    }
    __syncthreads();

    // ---- per-column inverse norms ----
    if (tid < NC) {
        float s = 0.f;
        const float* row = xs + tid * Dd;
        #pragma unroll 8
        for (int d = 0; d < Dd; d++) { float v = row[d]; s = fmaf(v, v, s); }
        inorm[tid] = __fdiv_rn(1.f, __fsqrt_rn(s) + EPSF);
    }
    // ---- ptok4 = ph4 @ pres_W2 + pres_b2 ----
    #pragma unroll 1
    for (int o = tid; o < 512; o += NT) {
        int c = o >> 7, d = o & 127;
        float s = pb2[d];
        const float* ph = ph4 + c*64;
        #pragma unroll 8
        for (int t = 0; t < 64; t++) s = fmaf(ph[t], pW2[t*128 + d], s);
        ptok4[o] = s;
    }
    __syncthreads();
    // ---- pcon = ptok4 @ fus_W1[1024:1152] ----
    #pragma unroll 1
    for (int o = tid; o < 1024; o += NT) {
        int c = o >> 8, q = o & 255;
        float s = 0.f;
        const float* pt = ptok4 + c*128;
        #pragma unroll 8
        for (int d = 0; d < 128; d++) s = fmaf(pt[d], fW1[(1024 + d)*256 + q], s);
        pcon[o] = s;
    }
    __syncthreads();

    // ---- hid accumulator mapping: warp = 16p x 128q, thread = 4p x 16q ----
    const int wid  = tid >> 5, lane = tid & 31;
    const int pbase = (wid >> 1) * 16 + (lane >> 3) * 4;  // first of 4 p
    const int qbase = (wid & 1) * 128 + (lane & 7) * 16;  // first of 16 q
    u64 acc[4][8];
    #pragma unroll
    for (int i = 0; i < 4; i++) {
        const int c = pcx[pbase + i];
        const float* pcr = pcon + c*256 + qbase;
        const float* fb  = fb1 + qbase;
        #pragma unroll
        for (int j = 0; j < 8; j++)
            acc[i][j] = pk2(fb[2*j] + pcr[2*j], fb[2*j+1] + pcr[2*j+1]);
    }

    const int mlp_idx[8] = {0, 1, 2, 3, 4, 4, 5, 5};

    #pragma unroll 1
    for (int k = 0; k < 8; k++) {
        const int w = mlp_idx[k];

        // stage W1_k (128x64) + compute feats
        stage8192(oW1 + w*8192, wb, tid);
        #pragma unroll 1
        for (int it = 0; it < 8; it++) {
            int o = tid + it*NT;
            int p = o >> 5, d4 = (o & 31) * 4;
            int ci = pi[p], cj = pj[p];
            float4 a4 = *(const float4*)(xs + ci*Dd + d4);
            float4 c4 = *(const float4*)(xs + cj*Dd + d4);
            float ni = inorm[ci], nj = inorm[cj];
            float4 f4;
            f4.x = featf(k, a4.x, c4.x, ni, nj);
            f4.y = featf(k, a4.y, c4.y, ni, nj);
            f4.z = featf(k, a4.z, c4.z, ni, nj);
            f4.w = featf(k, a4.w, c4.w, ni, nj);
            *(float4*)(feats + p*132 + d4) = f4;
        }
        __syncthreads();

        // h = relu(feats @ W1_k + b1_k) : thread = 2p x (2 halves x 4j)
        {
            const int jg = tid & 7, p2 = (tid >> 3) * 2;
            u64 hacc[2][2][2];
            #pragma unroll
            for (int h = 0; h < 2; h++) {
                int j0 = w*64 + h*32 + jg*4;
                u64 b01 = pk2(ob1[j0],   ob1[j0+1]);
                u64 b23 = pk2(ob1[j0+2], ob1[j0+3]);
                hacc[0][h][0] = b01; hacc[0][h][1] = b23;
                hacc[1][h][0] = b01; hacc[1][h][1] = b23;
            }
            #pragma unroll 2
            for (int d = 0; d < 128; d += 4) {
                float4 f0 = *(const float4*)(feats + p2*132 + d);
                float4 f1 = *(const float4*)(feats + (p2+1)*132 + d);
                #pragma unroll
                for (int dd = 0; dd < 4; dd++) {
                    u64 u0 = dup2((&f0.x)[dd]);
                    u64 u1 = dup2((&f1.x)[dd]);
                    #pragma unroll
                    for (int h = 0; h < 2; h++) {
                        ulonglong2 wv = *(const ulonglong2*)(wb + (d+dd)*64 + h*32 + jg*4);
                        fma2(hacc[0][h][0], u0, wv.x);
                        fma2(hacc[0][h][1], u0, wv.y);
                        fma2(hacc[1][h][0], u1, wv.x);
                        fma2(hacc[1][h][1], u1, wv.y);
                    }
                }
            }
            #pragma unroll
            for (int i = 0; i < 2; i++)
                #pragma unroll
                for (int h = 0; h < 2; h++) {
                    float4 v;
                    up2(hacc[i][h][0], v.x, v.y);
                    up2(hacc[i][h][1], v.z, v.w);
                    v.x = v.x > 0.f ? v.x : 0.f;
                    v.y = v.y > 0.f ? v.y : 0.f;
                    v.z = v.z > 0.f ? v.z : 0.f;
                    v.w = v.w > 0.f ? v.w : 0.f;
                    *(float4*)(hb + (p2+i)*68 + h*32 + jg*4) = v;
                }
        }
        __syncthreads();

        // stage W2_k (64x128)
        stage8192(oW2 + w*8192, wb, tid);
        __syncthreads();

        // tok = h @ W2_k + b2_k : thread = 2p x (4 quarters x 4d) ; writes tokb (alias feats)
        {
            const int dg = tid & 7, p2 = (tid >> 3) * 2;
            u64 tacc[2][4][2];
            #pragma unroll
            for (int qt = 0; qt < 4; qt++) {
                int d0 = w*128 + qt*32 + dg*4;
                u64 b01 = pk2(ob2[d0],   ob2[d0+1]);
                u64 b23 = pk2(ob2[d0+2], ob2[d0+3]);
                tacc[0][qt][0] = b01; tacc[0][qt][1] = b23;
                tacc[1][qt][0] = b01; tacc[1][qt][1] = b23;
            }
            #pragma unroll 1
            for (int jj = 0; jj < 64; jj += 4) {
                float4 h0 = *(const float4*)(hb + p2*68 + jj);
                float4 h1 = *(const float4*)(hb + (p2+1)*68 + jj);
                #pragma unroll
                for (int e = 0; e < 4; e++) {
                    u64 u0 = dup2((&h0.x)[e]);
                    u64 u1 = dup2((&h1.x)[e]);
                    #pragma unroll
                    for (int qt = 0; qt < 4; qt++) {
                        ulonglong2 wv = *(const ulonglong2*)(wb + (jj+e)*128 + qt*32 + dg*4);
                        fma2(tacc[0][qt][0], u0, wv.x);
                        fma2(tacc[0][qt][1], u0, wv.y);
                        fma2(tacc[1][qt][0], u1, wv.x);
                        fma2(tacc[1][qt][1], u1, wv.y);
                    }
                }
            }
            #pragma unroll
            for (int i = 0; i < 2; i++)
                #pragma unroll
                for (int qt = 0; qt < 4; qt++) {
                    float4 v;
                    up2(tacc[i][qt][0], v.x, v.y);
                    up2(tacc[i][qt][1], v.z, v.w);
                    *(float4*)(tokb + (p2+i)*132 + qt*32 + dg*4) = v;
                }
        }
        __syncthreads();

        // hid += tok_k @ fus_W1[k*128:(k+1)*128] ; fW1 staged in 32-row chunks
        #pragma unroll 1
        for (int ch = 0; ch < 4; ch++) {
            stage8192(fW1 + (size_t)(k*128 + ch*32) * 256, wb, tid);
            __syncthreads();
            #pragma unroll 1
            for (int c4 = 0; c4 < 8; c4++) {
                const int c0 = c4 * 4;
                float4 t[4];
                #pragma unroll
                for (int i = 0; i < 4; i++)
                    t[i] = *(const float4*)(tokb + (pbase+i)*132 + ch*32 + c0);
                #pragma unroll
                for (int e = 0; e < 4; e++) {
                    const float* wr = wb + (c0+e)*256 + qbase;
                    ulonglong2 w0 = *(const ulonglong2*)(wr);
                    ulonglong2 w1 = *(const ulonglong2*)(wr + 4);
                    ulonglong2 w2 = *(const ulonglong2*)(wr + 8);
                    ulonglong2 w3 = *(const ulonglong2*)(wr + 12);
                    #pragma unroll
                    for (int i = 0; i < 4; i++) {
                        u64 tv = dup2((&t[i].x)[e]);
                        fma2(acc[i][0], tv, w0.x);
                        fma2(acc[i][1], tv, w0.y);
                        fma2(acc[i][2], tv, w1.x);
                        fma2(acc[i][3], tv, w1.y);
                        fma2(acc[i][4], tv, w2.x);
                        fma2(acc[i][5], tv, w2.y);
                        fma2(acc[i][6], tv, w3.x);
                        fma2(acc[i][7], tv, w3.y);
                    }
                }
            }
            __syncthreads();
        }
    }

    // ---- relu(acc) -> hid (alias over xs+feats), stride 260 ----
    float* hid = sm + OFF_HID;
    #pragma unroll
    for (int i = 0; i < 4; i++) {
        float* hrow = hid + (pbase+i)*260 + qbase;
        #pragma unroll
        for (int j4 = 0; j4 < 4; j4++) {
            float4 v;
            up2(acc[i][2*j4],   v.x, v.y);
            up2(acc[i][2*j4+1], v.z, v.w);
            v.x = v.x > 0.f ? v.x : 0.f;
            v.y = v.y > 0.f ? v.y : 0.f;
            v.z = v.z > 0.f ? v.z : 0.f;
            v.w = v.w > 0.f ? v.w : 0.f;
            *(float4*)(hrow + j4*4) = v;
        }
    }
    __syncthreads();

    // ---- out = relu(hid) @ fus_W2 + fus_b2 : thread = 2p x (4 quarters x 4d) ----
    {
        const int dg = tid & 7, p2 = (tid >> 3) * 2;
        u64 oacc[2][4][2];
        #pragma unroll
        for (int qt = 0; qt < 4; qt++) {
            int d0 = qt*32 + dg*4;
            u64 b01 = pk2(fb2[d0],   fb2[d0+1]);
            u64 b23 = pk2(fb2[d0+2], fb2[d0+3]);
            oacc[0][qt][0] = b01; oacc[0][qt][1] = b23;
            oacc[1][qt][0] = b01; oacc[1][qt][1] = b23;
        }
        #pragma unroll 1
        for (int ch = 0; ch < 4; ch++) {
            stage8192(fW2 + (size_t)ch * 64 * 128, wb, tid);
            __syncthreads();
            #pragma unroll 1
            for (int qq = 0; qq < 64; qq += 4) {
                float4 h0 = *(const float4*)(hid + p2*260 + ch*64 + qq);
                float4 h1 = *(const float4*)(hid + (p2+1)*260 + ch*64 + qq);
                #pragma unroll
                for (int e = 0; e < 4; e++) {
                    u64 u0 = dup2((&h0.x)[e]);
                    u64 u1 = dup2((&h1.x)[e]);
                    #pragma unroll
                    for (int qt = 0; qt < 4; qt++) {
                        ulonglong2 wv = *(const ulonglong2*)(wb + (qq+e)*128 + qt*32 + dg*4);
                        fma2(oacc[0][qt][0], u0, wv.x);
                        fma2(oacc[0][qt][1], u0, wv.y);
                        fma2(oacc[1][qt][0], u1, wv.x);
                        fma2(oacc[1][qt][1], u1, wv.y);
                    }
                }
            }
            __syncthreads();
        }
        #pragma unroll
        for (int i = 0; i < 2; i++) {
            int p = p2 + i;
            float* orow = out + ((size_t)(b*Pp + p0 + p)) * 128;
            #pragma unroll
            for (int qt = 0; qt < 4; qt++) {
                float4 v;
                up2(oacc[i][qt][0], v.x, v.y);
                up2(oacc[i][qt][1], v.z, v.w);
                *(float4*)(orow + qt*32 + dg*4) = v;
            }
        }
    }
}

extern "C" void kernel_launch(void* const* d_in, const int* in_sizes, int n_in,
                              void* d_out, int out_size) {
    const float* x        = (const float*)d_in[0];
    const int*   presence = (const int*)d_in[1];
    const int*   idx_i    = (const int*)d_in[2];
    const int*   idx_j    = (const int*)d_in[3];
    const float* oW1      = (const float*)d_in[4];
    const float* ob1      = (const float*)d_in[5];
    const float* oW2      = (const float*)d_in[6];
    const float* ob2      = (const float*)d_in[7];
    const float* pW1      = (const float*)d_in[8];
    const float* pb1      = (const float*)d_in[9];
    const float* pW2      = (const float*)d_in[10];
    const float* pb2      = (const float*)d_in[11];
    const float* fW1      = (const float*)d_in[12];
    const float* fb1      = (const float*)d_in[13];
    const float* fW2      = (const float*)d_in[14];
    const float* fb2      = (const float*)d_in[15];

    cudaFuncSetAttribute(dre_kernel, cudaFuncAttributeMaxDynamicSharedMemorySize, SMEM_BYTES);
    dim3 grid(42, 64);
    dre_kernel<<<grid, NT, SMEM_BYTES>>>(x, presence, idx_i, idx_j,
                                         oW1, ob1, oW2, ob2,
                                         pW1, pb1, pW2, pb2,
                                         fW1, fb1, fW2, fb2,
                                         (float*)d_out);
}

// round 4
// speedup vs baseline: 1.8316x; 1.8316x over previous
#include <cuda_runtime.h>

// DynamicRelationshipExtractor — GB300 sm_103a, round 4
// Base = round 2 (3245us). Single change: hid-update GEMM retiled to
// warp = 16p x 128q, thread = 4p x 16q with a conflict-free layout:
//   weights: 8 lanes x 16B contiguous 128B, 4-way multicast -> 1 wavefront
//   acts:    4 consecutive rows per lane-group (bank offset 4) -> 1 wavefront
// Halves the hid-loop L1 wavefronts vs round 2.

#define EPSF 1e-6f

static const int NC = 64;
static const int Dd = 128;
static const int Pp = 2016;
static const int TP = 64;

typedef unsigned long long u64;

__device__ __forceinline__ u64 pk2(float x, float y) {
    u64 r; asm("mov.b64 %0, {%1, %2};" : "=l"(r) : "f"(x), "f"(y)); return r;
}
__device__ __forceinline__ u64 dup2(float x) {
    u64 r; asm("mov.b64 %0, {%1, %1};" : "=l"(r) : "f"(x)); return r;
}
__device__ __forceinline__ void fma2(u64 &d, u64 a, u64 b) {
    asm("fma.rn.f32x2 %0, %1, %2, %0;" : "+l"(d) : "l"(a), "l"(b));
}
__device__ __forceinline__ void up2(u64 v, float &x, float &y) {
    asm("mov.b64 {%0, %1}, %2;" : "=f"(x), "=f"(y) : "l"(v));
}

// shared layout (floats)
#define OFF_XS     0
#define OFF_FEATS  (OFF_XS + 64*128)        // 8192, stride 132
#define OFF_TOKB   (OFF_FEATS + 64*132)     // stride 132
#define OFF_HB     (OFF_TOKB + 64*132)      // stride 68
#define OFF_WB     (OFF_HB + 64*68)         // 8192-float weight scratch
#define OFF_PCON   (OFF_WB + 8192)
#define OFF_PTOK4  (OFF_PCON + 4*256)
#define OFF_PH4    (OFF_PTOK4 + 4*128)
#define OFF_INORM  (OFF_PH4 + 4*64)
#define OFF_END    (OFF_INORM + 64)
#define OFF_HID    OFF_FEATS                // alias: 64*260 <= feats+tokb (16896)
#define SMEM_FLOATS OFF_END
#define SMEM_BYTES (SMEM_FLOATS*4 + 3*64*4)

__device__ __forceinline__ float featf(int k, float a, float c, float ni, float nj) {
    switch (k) {
        case 0: return a * c;
        case 1: return a + c;
        case 2: return (a * ni) * (c * nj);
        case 3: return fabsf(a - c);
        case 4: return a - c;
        case 5: return c - a;
        case 6: return __fdiv_rn(a, c + EPSF);
        default: return __fdiv_rn(c, a + EPSF);
    }
}

__global__ void __launch_bounds__(256, 1)
dre_kernel(const float* __restrict__ x, const int* __restrict__ presence,
           const int* __restrict__ idx_i, const int* __restrict__ idx_j,
           const float* __restrict__ oW1, const float* __restrict__ ob1,
           const float* __restrict__ oW2, const float* __restrict__ ob2,
           const float* __restrict__ pW1, const float* __restrict__ pb1,
           const float* __restrict__ pW2, const float* __restrict__ pb2,
           const float* __restrict__ fW1, const float* __restrict__ fb1,
           const float* __restrict__ fW2, const float* __restrict__ fb2,
           float* __restrict__ out)
{
    extern __shared__ float sm[];
    float* xs    = sm + OFF_XS;
    float* feats = sm + OFF_FEATS;
    float* tokb  = sm + OFF_TOKB;
    float* hb    = sm + OFF_HB;
    float* wb    = sm + OFF_WB;
    float* pcon  = sm + OFF_PCON;
    float* ptok4 = sm + OFF_PTOK4;
    float* ph4   = sm + OFF_PH4;
    float* inorm = sm + OFF_INORM;
    int*   pi    = (int*)(sm + OFF_END);
    int*   pj    = pi + 64;
    int*   pcx   = pj + 64;

    const int tid = threadIdx.x;
    const int b   = blockIdx.x >> 5;
    const int p0  = (blockIdx.x & 31) * TP;

    // ---- load x[b] into shared ----
    {
        const float4* src = (const float4*)(x + (size_t)b * NC * Dd);
        float4* dst = (float4*)xs;
        #pragma unroll
        for (int i = 0; i < 8; i++) dst[tid + i*256] = src[tid + i*256];
    }
    // ---- pair indices + presence class ----
    if (tid < TP) {
        int pp = p0 + tid; if (pp >= Pp) pp = Pp - 1;
        int ii = idx_i[pp], jj = idx_j[pp];
        pi[tid] = ii; pj[tid] = jj;
        int pa = presence[b*NC + ii], pb_ = presence[b*NC + jj];
        pcx[tid] = pa ? (pb_ ? 0 : 1) : (pb_ ? 2 : 3);
    }
    // ---- ph4 = relu(pres_W1[c] + pres_b1) ----
    {
        int c = tid >> 6, t = tid & 63;
        float v = pW1[c*64 + t] + pb1[t];
        ph4[tid] = v > 0.f ? v : 0.f;
    }
    __syncthreads();

    // ---- per-column inverse norms ----
    if (tid < NC) {
        float s = 0.f;
        const float* row = xs + tid * Dd;
        #pragma unroll 8
        for (int d = 0; d < Dd; d++) { float v = row[d]; s = fmaf(v, v, s); }
        inorm[tid] = __fdiv_rn(1.f, __fsqrt_rn(s) + EPSF);
    }
    // ---- ptok4 = ph4 @ pres_W2 + pres_b2 ----
    for (int o = tid; o < 512; o += 256) {
        int c = o >> 7, d = o & 127;
        float s = pb2[d];
        const float* ph = ph4 + c*64;
        #pragma unroll 8
        for (int t = 0; t < 64; t++) s = fmaf(ph[t], pW2[t*128 + d], s);
        ptok4[o] = s;
    }
    __syncthreads();
    // ---- pcon = ptok4 @ fus_W1[1024:1152] ----
    for (int o = tid; o < 1024; o += 256) {
        int c = o >> 8, q = o & 255;
        float s = 0.f;
        const float* pt = ptok4 + c*128;
        #pragma unroll 8
        for (int d = 0; d < 128; d++) s = fmaf(pt[d], fW1[(1024 + d)*256 + q], s);
        pcon[o] = s;
    }
    __syncthreads();

    // ---- hid accumulator: warp = 16p x 128q, thread = 4p x 16q ----
    // p rows owned: prow + i*4 (i=0..3); q owned: qh*128 + eb*32 + qq0 (+0..3)
    const int wid  = tid >> 5, lane = tid & 31;
    const int pt   = wid >> 1, qh = wid & 1;
    const int prow = pt*16 + (lane >> 3);
    const int qq0  = (lane & 7) * 4;
    u64 acc[4][4][2];
    #pragma unroll
    for (int i = 0; i < 4; i++) {
        const int c = pcx[prow + i*4];
        #pragma unroll
        for (int eb = 0; eb < 4; eb++) {
            int q = qh*128 + eb*32 + qq0;
            const float* pcr = pcon + c*256 + q;
            acc[i][eb][0] = pk2(fb1[q]   + pcr[0], fb1[q+1] + pcr[1]);
            acc[i][eb][1] = pk2(fb1[q+2] + pcr[2], fb1[q+3] + pcr[3]);
        }
    }

    const int mlp_idx[8] = {0, 1, 2, 3, 4, 4, 5, 5};

    #pragma unroll 1
    for (int k = 0; k < 8; k++) {
        const int w = mlp_idx[k];

        // stage W1_k (128x64) + compute feats
        {
            const float4* src = (const float4*)(oW1 + w*8192);
            float4* dst = (float4*)wb;
            #pragma unroll
            for (int i = 0; i < 8; i++) dst[tid + i*256] = src[tid + i*256];
        }
        #pragma unroll 1
        for (int it = 0; it < 8; it++) {
            int o = tid + it*256;
            int p = o >> 5, d4 = (o & 31) * 4;
            int ci = pi[p], cj = pj[p];
            float4 a4 = *(const float4*)(xs + ci*Dd + d4);
            float4 c4 = *(const float4*)(xs + cj*Dd + d4);
            float ni = inorm[ci], nj = inorm[cj];
            float4 f4;
            f4.x = featf(k, a4.x, c4.x, ni, nj);
            f4.y = featf(k, a4.y, c4.y, ni, nj);
            f4.z = featf(k, a4.z, c4.z, ni, nj);
            f4.w = featf(k, a4.w, c4.w, ni, nj);
            *(float4*)(feats + p*132 + d4) = f4;
        }
        __syncthreads();

        // h = relu(feats @ W1_k + b1_k) : thread = 2p x (2 halves x 4j)
        {
            const int jg = tid & 7, p2 = (tid >> 3) * 2;
            u64 hacc[2][2][2];
            #pragma unroll
            for (int h = 0; h < 2; h++) {
                int j0 = w*64 + h*32 + jg*4;
                u64 b01 = pk2(ob1[j0],   ob1[j0+1]);
                u64 b23 = pk2(ob1[j0+2], ob1[j0+3]);
                hacc[0][h][0] = b01; hacc[0][h][1] = b23;
                hacc[1][h][0] = b01; hacc[1][h][1] = b23;
            }
            #pragma unroll 2
            for (int d = 0; d < 128; d += 4) {
                float4 f0 = *(const float4*)(feats + p2*132 + d);
                float4 f1 = *(const float4*)(feats + (p2+1)*132 + d);
                #pragma unroll
                for (int dd = 0; dd < 4; dd++) {
                    u64 u0 = dup2((&f0.x)[dd]);
                    u64 u1 = dup2((&f1.x)[dd]);
                    #pragma unroll
                    for (int h = 0; h < 2; h++) {
                        ulonglong2 wv = *(const ulonglong2*)(wb + (d+dd)*64 + h*32 + jg*4);
                        fma2(hacc[0][h][0], u0, wv.x);
                        fma2(hacc[0][h][1], u0, wv.y);
                        fma2(hacc[1][h][0], u1, wv.x);
                        fma2(hacc[1][h][1], u1, wv.y);
                    }
                }
            }
            #pragma unroll
            for (int i = 0; i < 2; i++)
                #pragma unroll
                for (int h = 0; h < 2; h++) {
                    float4 v;
                    up2(hacc[i][h][0], v.x, v.y);
                    up2(hacc[i][h][1], v.z, v.w);
                    v.x = v.x > 0.f ? v.x : 0.f;
                    v.y = v.y > 0.f ? v.y : 0.f;
                    v.z = v.z > 0.f ? v.z : 0.f;
                    v.w = v.w > 0.f ? v.w : 0.f;
                    *(float4*)(hb + (p2+i)*68 + h*32 + jg*4) = v;
                }
        }
        __syncthreads();

        // stage W2_k (64x128)
        {
            const float4* src = (const float4*)(oW2 + w*8192);
            float4* dst = (float4*)wb;
            #pragma unroll
            for (int i = 0; i < 8; i++) dst[tid + i*256] = src[tid + i*256];
        }
        __syncthreads();

        // tok = h @ W2_k + b2_k : thread = 2p x (4 quarters x 4d)
        {
            const int dg = tid & 7, p2 = (tid >> 3) * 2;
            u64 tacc[2][4][2];
            #pragma unroll
            for (int qt = 0; qt < 4; qt++) {
                int d0 = w*128 + qt*32 + dg*4;
                u64 b01 = pk2(ob2[d0],   ob2[d0+1]);
                u64 b23 = pk2(ob2[d0+2], ob2[d0+3]);
                tacc[0][qt][0] = b01; tacc[0][qt][1] = b23;
                tacc[1][qt][0] = b01; tacc[1][qt][1] = b23;
            }
            #pragma unroll 1
            for (int jj = 0; jj < 64; jj += 4) {
                float4 h0 = *(const float4*)(hb + p2*68 + jj);
                float4 h1 = *(const float4*)(hb + (p2+1)*68 + jj);
                #pragma unroll
                for (int e = 0; e < 4; e++) {
                    u64 u0 = dup2((&h0.x)[e]);
                    u64 u1 = dup2((&h1.x)[e]);
                    #pragma unroll
                    for (int qt = 0; qt < 4; qt++) {
                        ulonglong2 wv = *(const ulonglong2*)(wb + (jj+e)*128 + qt*32 + dg*4);
                        fma2(tacc[0][qt][0], u0, wv.x);
                        fma2(tacc[0][qt][1], u0, wv.y);
                        fma2(tacc[1][qt][0], u1, wv.x);
                        fma2(tacc[1][qt][1], u1, wv.y);
                    }
                }
            }
            #pragma unroll
            for (int i = 0; i < 2; i++)
                #pragma unroll
                for (int qt = 0; qt < 4; qt++) {
                    float4 v;
                    up2(tacc[i][qt][0], v.x, v.y);
                    up2(tacc[i][qt][1], v.z, v.w);
                    *(float4*)(tokb + (p2+i)*132 + qt*32 + dg*4) = v;
                }
        }
        __syncthreads();

        // hid += tok_k @ fus_W1[k*128:(k+1)*128] (staged in 32-row chunks)
        #pragma unroll 1
        for (int ch = 0; ch < 4; ch++) {
            {
                const float4* src = (const float4*)(fW1 + (size_t)(k*128 + ch*32) * 256);
                float4* dst = (float4*)wb;
                #pragma unroll
                for (int i = 0; i < 8; i++) dst[tid + i*256] = src[tid + i*256];
            }
            __syncthreads();
            #pragma unroll 1
            for (int c4 = 0; c4 < 8; c4++) {
                const int c0 = c4 * 4;
                float4 t[4];
                #pragma unroll
                for (int i = 0; i < 4; i++)
                    t[i] = *(const float4*)(tokb + (prow + i*4)*132 + ch*32 + c0);
                #pragma unroll
                for (int e = 0; e < 4; e++) {
                    const float* wr = wb + (c0+e)*256 + qh*128 + qq0;
                    ulonglong2 w0 = *(const ulonglong2*)(wr);
                    ulonglong2 w1 = *(const ulonglong2*)(wr + 32);
                    ulonglong2 w2 = *(const ulonglong2*)(wr + 64);
                    ulonglong2 w3 = *(const ulonglong2*)(wr + 96);
                    #pragma unroll
                    for (int i = 0; i < 4; i++) {
                        u64 tv = dup2((&t[i].x)[e]);
                        fma2(acc[i][0][0], tv, w0.x);
                        fma2(acc[i][0][1], tv, w0.y);
                        fma2(acc[i][1][0], tv, w1.x);
                        fma2(acc[i][1][1], tv, w1.y);
                        fma2(acc[i][2][0], tv, w2.x);
                        fma2(acc[i][2][1], tv, w2.y);
                        fma2(acc[i][3][0], tv, w3.x);
                        fma2(acc[i][3][1], tv, w3.y);
                    }
                }
            }
            __syncthreads();
        }
    }

    // ---- relu(acc) -> hid (aliased over feats+tokb), stride 260 ----
    float* hid = sm + OFF_HID;
    #pragma unroll
    for (int i = 0; i < 4; i++) {
        float* hrow = hid + (prow + i*4)*260 + qh*128 + qq0;
        #pragma unroll
        for (int eb = 0; eb < 4; eb++) {
            float4 v;
            up2(acc[i][eb][0], v.x, v.y);
            up2(acc[i][eb][1], v.z, v.w);
            v.x = v.x > 0.f ? v.x : 0.f;
            v.y = v.y > 0.f ? v.y : 0.f;
            v.z = v.z > 0.f ? v.z : 0.f;
            v.w = v.w > 0.f ? v.w : 0.f;
            *(float4*)(hrow + eb*32) = v;
        }
    }
    __syncthreads();

    // ---- out = relu(hid) @ fus_W2 + fus_b2 : thread = 2p x (4 quarters x 4d) ----
    {
        const int dg = tid & 7, p2 = (tid >> 3) * 2;
        u64 oacc[2][4][2];
        #pragma unroll
        for (int qt = 0; qt < 4; qt++) {
            int d0 = qt*32 + dg*4;
            u64 b01 = pk2(fb2[d0],   fb2[d0+1]);
            u64 b23 = pk2(fb2[d0+2], fb2[d0+3]);
            oacc[0][qt][0] = b01; oacc[0][qt][1] = b23;
            oacc[1][qt][0] = b01; oacc[1][qt][1] = b23;
        }
        #pragma unroll 1
        for (int ch = 0; ch < 4; ch++) {
            {
                const float4* src = (const float4*)(fW2 + (size_t)ch * 64 * 128);
                float4* dst = (float4*)wb;
                #pragma unroll
                for (int i = 0; i < 8; i++) dst[tid + i*256] = src[tid + i*256];
            }
            __syncthreads();
            #pragma unroll 1
            for (int qq = 0; qq < 64; qq += 4) {
                float4 h0 = *(const float4*)(hid + p2*260 + ch*64 + qq);
                float4 h1 = *(const float4*)(hid + (p2+1)*260 + ch*64 + qq);
                #pragma unroll
                for (int e = 0; e < 4; e++) {
                    u64 u0 = dup2((&h0.x)[e]);
                    u64 u1 = dup2((&h1.x)[e]);
                    #pragma unroll
                    for (int qt = 0; qt < 4; qt++) {
                        ulonglong2 wv = *(const ulonglong2*)(wb + (qq+e)*128 + qt*32 + dg*4);
                        fma2(oacc[0][qt][0], u0, wv.x);
                        fma2(oacc[0][qt][1], u0, wv.y);
                        fma2(oacc[1][qt][0], u1, wv.x);
                        fma2(oacc[1][qt][1], u1, wv.y);
                    }
                }
            }
            __syncthreads();
        }
        #pragma unroll
        for (int i = 0; i < 2; i++) {
            int p = p2 + i;
            if (p0 + p < Pp) {
                float* orow = out + ((size_t)(b*Pp + p0 + p)) * 128;
                #pragma unroll
                for (int qt = 0; qt < 4; qt++) {
                    float4 v;
                    up2(oacc[i][qt][0], v.x, v.y);
                    up2(oacc[i][qt][1], v.z, v.w);
                    *(float4*)(orow + qt*32 + dg*4) = v;
                }
            }
        }
    }
}

extern "C" void kernel_launch(void* const* d_in, const int* in_sizes, int n_in,
                              void* d_out, int out_size) {
    const float* x        = (const float*)d_in[0];
    const int*   presence = (const int*)d_in[1];
    const int*   idx_i    = (const int*)d_in[2];
    const int*   idx_j    = (const int*)d_in[3];
    const float* oW1      = (const float*)d_in[4];
    const float* ob1      = (const float*)d_in[5];
    const float* oW2      = (const float*)d_in[6];
    const float* ob2      = (const float*)d_in[7];
    const float* pW1      = (const float*)d_in[8];
    const float* pb1      = (const float*)d_in[9];
    const float* pW2      = (const float*)d_in[10];
    const float* pb2      = (const float*)d_in[11];
    const float* fW1      = (const float*)d_in[12];
    const float* fb1      = (const float*)d_in[13];
    const float* fW2      = (const float*)d_in[14];
    const float* fb2      = (const float*)d_in[15];

    cudaFuncSetAttribute(dre_kernel, cudaFuncAttributeMaxDynamicSharedMemorySize, SMEM_BYTES);
    dre_kernel<<<2048, 256, SMEM_BYTES>>>(x, presence, idx_i, idx_j,
                                          oW1, ob1, oW2, ob2,
                                          pW1, pb1, pW2, pb2,
                                          fW1, fb1, fW2, fb2,
                                          (float*)d_out);
}